// round 1
// baseline (speedup 1.0000x reference)
#include <cuda_runtime.h>
#include <math.h>

#define B  1024
#define S  200
#define HD 256
#define AD 128

// ---------------- scratch (static device globals; no allocations) ----------
__device__ float g_tproj[B * AD];
__device__ float g_scores[B * S];
__device__ float g_att[S * B];                       // att transposed [t][b]
__device__ float g_X[3ull * S * B * HD];             // [gate][t][b][h], gates: r,z,n
__device__ float g_h[B * HD];
__device__ float g_rh[B * HD];
__device__ float g_z[B * HD];
__device__ unsigned int g_barcnt;

static const size_t TB  = (size_t)B * HD;            // 262144
static const size_t XSZ = (size_t)S * B * HD;        // 52,428,800

__device__ __forceinline__ float sigf(float x) { return 1.0f / (1.0f + expf(-x)); }

// ---------------- reset barrier counter (fresh every launch/replay) --------
__global__ void k_reset() { g_barcnt = 0u; }

// ---------------- tproj[b,a] = b1[a] + sum_d tgt[b,d]*W1[a,256+d] ----------
__global__ void k_tproj(const float* __restrict__ tgt,
                        const float* __restrict__ W1,
                        const float* __restrict__ b1) {
    __shared__ float ts[HD];
    int b = blockIdx.x, a = threadIdx.x;
    for (int i = threadIdx.x; i < HD; i += 128) ts[i] = tgt[(size_t)b * HD + i];
    __syncthreads();
    float s = b1[a];
    const float* w = W1 + (size_t)a * 512 + 256;
#pragma unroll 8
    for (int k = 0; k < HD; k++) s += ts[k] * w[k];
    g_tproj[b * AD + a] = s;
}

// ---------------- scores[b,s] = sum_a W2[a]*relu(hid@W1h + tproj) ----------
// 8 rows (s) per CTA, 128 threads = one attention unit 'a' per thread.
__global__ void k_scores(const float* __restrict__ hs,
                         const float* __restrict__ W1,
                         const float* __restrict__ W2) {
    __shared__ float sh[8 * HD];
    __shared__ float red[4][8];
    int b = blockIdx.x / 25;
    int s0 = (blockIdx.x % 25) * 8;
    int a = threadIdx.x;

    const float* base = hs + ((size_t)b * S + s0) * HD;
    for (int i = a; i < (8 * HD) / 4; i += 128)
        ((float4*)sh)[i] = ((const float4*)base)[i];
    __syncthreads();

    float acc[8];
#pragma unroll
    for (int r = 0; r < 8; r++) acc[r] = 0.0f;

    const float* w = W1 + (size_t)a * 512;      // hidden part of W1 row a
    for (int k = 0; k < HD; k += 4) {
        float4 wv = *(const float4*)(w + k);
#pragma unroll
        for (int r = 0; r < 8; r++) {
            float4 hv = *(const float4*)(sh + r * HD + k);
            acc[r] += wv.x * hv.x + wv.y * hv.y + wv.z * hv.z + wv.w * hv.w;
        }
    }
    float tp = g_tproj[b * AD + a];
    float w2 = W2[a];
#pragma unroll
    for (int r = 0; r < 8; r++) {
        float v = fmaxf(acc[r] + tp, 0.0f) * w2;
#pragma unroll
        for (int o = 16; o; o >>= 1) v += __shfl_down_sync(0xffffffffu, v, o);
        if ((a & 31) == 0) red[a >> 5][r] = v;
    }
    __syncthreads();
    if (a < 8) {
        float sres = red[0][a] + red[1][a] + red[2][a] + red[3][a];
        g_scores[b * S + s0 + a] = sres;
    }
}

// ---------------- masked softmax over S, output transposed [t][b] ----------
__global__ void k_softmax(const int* __restrict__ lengths) {
    __shared__ float red[256];
    int b = blockIdx.x, s = threadIdx.x;
    int len = lengths[b];
    float sc = -3.0e38f;
    if (s < S) sc = (s < len) ? g_scores[b * S + s] : -1e9f;
    red[s] = sc; __syncthreads();
    for (int o = 128; o; o >>= 1) {
        if (s < o) red[s] = fmaxf(red[s], red[s + o]);
        __syncthreads();
    }
    float mx = red[0]; __syncthreads();
    float e = (s < S) ? expf(sc - mx) : 0.0f;
    red[s] = e; __syncthreads();
    for (int o = 128; o; o >>= 1) {
        if (s < o) red[s] += red[s + o];
        __syncthreads();
    }
    float inv = 1.0f / red[0];
    if (s < S) g_att[s * B + b] = e * inv;
}

// ---------------- X[g][t][b][h] = hs[b,t,:] @ Wg[:, :256]^T + bg ----------
// 64x64 tile GEMM over rows=(b,s) cols=(gate,h), K=256 in 64-chunks.
__global__ void __launch_bounds__(256) k_xproj(
    const float* __restrict__ hs,
    const float* __restrict__ Wr, const float* __restrict__ br,
    const float* __restrict__ Wz, const float* __restrict__ bz,
    const float* __restrict__ Wn, const float* __restrict__ bn) {
    __shared__ float As[64 * 64];   // [row][k]
    __shared__ float Ws[64 * 64];   // [k][col]
    int bx = blockIdx.x;            // 0..11 : gate = bx/4, h0 = (bx%4)*64
    int by = blockIdx.y;            // 0..3199 row tile
    int g  = bx >> 2;
    int h0 = (bx & 3) * 64;
    const float* W    = (g == 0) ? Wr : (g == 1) ? Wz : Wn;
    const float* bias = (g == 0) ? br : (g == 1) ? bz : bn;

    int tid = threadIdx.x;
    int tx = tid & 15, ty = tid >> 4;
    float acc[4][4];
#pragma unroll
    for (int i = 0; i < 4; i++)
#pragma unroll
        for (int j = 0; j < 4; j++) acc[i][j] = 0.0f;

    const float* Abase = hs + (size_t)by * 64 * HD;
    for (int kc = 0; kc < HD; kc += 64) {
        for (int i = tid; i < 64 * 16; i += 256) {         // A chunk, float4
            int r = i >> 4, kv = i & 15;
            *(float4*)&As[r * 64 + kv * 4] =
                *(const float4*)&Abase[(size_t)r * HD + kc + kv * 4];
        }
        for (int i = tid; i < 64 * 16; i += 256) {         // W chunk -> k-major
            int c = i >> 4, kv = i & 15;
            float4 w = *(const float4*)&W[(size_t)(h0 + c) * 512 + kc + kv * 4];
            Ws[(kv * 4 + 0) * 64 + c] = w.x;
            Ws[(kv * 4 + 1) * 64 + c] = w.y;
            Ws[(kv * 4 + 2) * 64 + c] = w.z;
            Ws[(kv * 4 + 3) * 64 + c] = w.w;
        }
        __syncthreads();
#pragma unroll 8
        for (int k = 0; k < 64; k++) {
            float4 wv = *(const float4*)&Ws[k * 64 + tx * 4];
            float a0 = As[(ty * 4 + 0) * 64 + k];
            float a1 = As[(ty * 4 + 1) * 64 + k];
            float a2 = As[(ty * 4 + 2) * 64 + k];
            float a3 = As[(ty * 4 + 3) * 64 + k];
            acc[0][0] += a0 * wv.x; acc[0][1] += a0 * wv.y; acc[0][2] += a0 * wv.z; acc[0][3] += a0 * wv.w;
            acc[1][0] += a1 * wv.x; acc[1][1] += a1 * wv.y; acc[1][2] += a1 * wv.z; acc[1][3] += a1 * wv.w;
            acc[2][0] += a2 * wv.x; acc[2][1] += a2 * wv.y; acc[2][2] += a2 * wv.z; acc[2][3] += a2 * wv.w;
            acc[3][0] += a3 * wv.x; acc[3][1] += a3 * wv.y; acc[3][2] += a3 * wv.z; acc[3][3] += a3 * wv.w;
        }
        __syncthreads();
    }
    float4 bv = *(const float4*)&bias[h0 + tx * 4];
#pragma unroll
    for (int i = 0; i < 4; i++) {
        int rIdx = by * 64 + ty * 4 + i;
        int b = rIdx / S, s = rIdx % S;
        float4 o;
        o.x = acc[i][0] + bv.x; o.y = acc[i][1] + bv.y;
        o.z = acc[i][2] + bv.z; o.w = acc[i][3] + bv.w;
        *(float4*)&g_X[(size_t)g * XSZ + ((size_t)s * B + b) * HD + h0 + tx * 4] = o;
    }
}

// ---------------- persistent AUGRU scan -----------------------------------
#define NCTA 128

__device__ __forceinline__ void gridbar(unsigned int target) {
    __threadfence();
    __syncthreads();
    if (threadIdx.x == 0) {
        atomicAdd(&g_barcnt, 1u);
        while (*(volatile unsigned int*)&g_barcnt < target) { }
        __threadfence();
    }
    __syncthreads();
}

__global__ void __launch_bounds__(256, 1) k_recur(
    const float* __restrict__ Wr, const float* __restrict__ Wz,
    const float* __restrict__ Wn, float* __restrict__ out) {
    extern __shared__ float smem[];
    float* Ws1 = smem;                       // [256][64]  phase1 weight (k-major)
    float* Ws2 = smem + 256 * 64;            // [256][32]  phase2 weight (k-major)
    float* As  = smem + 256 * 64 + 256 * 32; // [64][256]  input tile

    int tid = threadIdx.x;
    int bid = blockIdx.x;        // 0..127
    int rt  = bid >> 3;          // row tile 0..15 (64 batch rows each)
    int ct  = bid & 7;           // col tile

    // --- persistent weight tiles ---
    // phase1: stacked [Wr_h ; Wz_h] cols ct*64 .. +63
    {
        const float* Wg1 = (ct < 4) ? Wr : Wz;
        int hbase = (ct < 4) ? ct * 64 : (ct - 4) * 64;
        for (int i = tid; i < 64 * 64; i += 256) {
            int c = i >> 6, kv = i & 63;
            float4 w = *(const float4*)&Wg1[(size_t)(hbase + c) * 512 + 256 + kv * 4];
            Ws1[(kv * 4 + 0) * 64 + c] = w.x;
            Ws1[(kv * 4 + 1) * 64 + c] = w.y;
            Ws1[(kv * 4 + 2) * 64 + c] = w.z;
            Ws1[(kv * 4 + 3) * 64 + c] = w.w;
        }
        // phase2: Wn_h cols ct*32 .. +31
        for (int i = tid; i < 32 * 64; i += 256) {
            int c = i >> 6, kv = i & 63;
            float4 w = *(const float4*)&Wn[(size_t)(ct * 32 + c) * 512 + 256 + kv * 4];
            Ws2[(kv * 4 + 0) * 32 + c] = w.x;
            Ws2[(kv * 4 + 1) * 32 + c] = w.y;
            Ws2[(kv * 4 + 2) * 32 + c] = w.z;
            Ws2[(kv * 4 + 3) * 32 + c] = w.w;
        }
    }
    // zero h
    {
        float4 zf = make_float4(0.f, 0.f, 0.f, 0.f);
        float4* hp = (float4*)(g_h + (size_t)bid * 2048);
        for (int i = tid; i < 512; i += 256) hp[i] = zf;
    }
    unsigned int tgt = NCTA;
    gridbar(tgt); tgt += NCTA;

    int tx = tid & 15, ty = tid >> 4;   // 16x16 thread grid

    for (int t = 0; t < S; t++) {
        // ================= phase 1: [r|z] = sigmoid(h @ W1 + X) ============
        {
            const float4* src = (const float4*)(g_h + (size_t)rt * 64 * HD);
            float4* dst = (float4*)As;
            for (int i = tid; i < 4096; i += 256) dst[i] = __ldcg(src + i);
        }
        __syncthreads();
        float acc[4][4];
#pragma unroll
        for (int i = 0; i < 4; i++)
#pragma unroll
            for (int j = 0; j < 4; j++) acc[i][j] = 0.0f;
#pragma unroll 4
        for (int k = 0; k < HD; k++) {
            float4 wv = *(const float4*)&Ws1[k * 64 + tx * 4];
            float a0 = As[(ty * 4 + 0) * HD + k];
            float a1 = As[(ty * 4 + 1) * HD + k];
            float a2 = As[(ty * 4 + 2) * HD + k];
            float a3 = As[(ty * 4 + 3) * HD + k];
            acc[0][0] += a0 * wv.x; acc[0][1] += a0 * wv.y; acc[0][2] += a0 * wv.z; acc[0][3] += a0 * wv.w;
            acc[1][0] += a1 * wv.x; acc[1][1] += a1 * wv.y; acc[1][2] += a1 * wv.z; acc[1][3] += a1 * wv.w;
            acc[2][0] += a2 * wv.x; acc[2][1] += a2 * wv.y; acc[2][2] += a2 * wv.z; acc[2][3] += a2 * wv.w;
            acc[3][0] += a3 * wv.x; acc[3][1] += a3 * wv.y; acc[3][2] += a3 * wv.z; acc[3][3] += a3 * wv.w;
        }
        if (ct < 4) {
            // r gate -> write rh = sigmoid(.) * h
            int hb = ct * 64 + tx * 4;
            const float* XrT = g_X + (size_t)t * TB;
#pragma unroll
            for (int i = 0; i < 4; i++) {
                int b = rt * 64 + ty * 4 + i;
                float4 xv = *(const float4*)&XrT[(size_t)b * HD + hb];
                float4 hv = *(const float4*)&As[(ty * 4 + i) * HD + hb];
                float4 o;
                o.x = sigf(acc[i][0] + xv.x) * hv.x;
                o.y = sigf(acc[i][1] + xv.y) * hv.y;
                o.z = sigf(acc[i][2] + xv.z) * hv.z;
                o.w = sigf(acc[i][3] + xv.w) * hv.w;
                __stcg((float4*)&g_rh[(size_t)b * HD + hb], o);
            }
        } else {
            // z gate -> z = sigmoid(.) * att
            int hb = (ct - 4) * 64 + tx * 4;
            const float* XzT = g_X + XSZ + (size_t)t * TB;
#pragma unroll
            for (int i = 0; i < 4; i++) {
                int b = rt * 64 + ty * 4 + i;
                float av = g_att[t * B + b];
                float4 xv = *(const float4*)&XzT[(size_t)b * HD + hb];
                float4 o;
                o.x = sigf(acc[i][0] + xv.x) * av;
                o.y = sigf(acc[i][1] + xv.y) * av;
                o.z = sigf(acc[i][2] + xv.z) * av;
                o.w = sigf(acc[i][3] + xv.w) * av;
                __stcg((float4*)&g_z[(size_t)b * HD + hb], o);
            }
        }
        gridbar(tgt); tgt += NCTA;

        // ================= phase 2: n = tanh(rh @ Wn_h + Xn); h update =====
        {
            const float4* src = (const float4*)(g_rh + (size_t)rt * 64 * HD);
            float4* dst = (float4*)As;
            for (int i = tid; i < 4096; i += 256) dst[i] = __ldcg(src + i);
        }
        __syncthreads();
        float acc2[4][2];
#pragma unroll
        for (int i = 0; i < 4; i++) { acc2[i][0] = 0.0f; acc2[i][1] = 0.0f; }
#pragma unroll 4
        for (int k = 0; k < HD; k++) {
            float2 wv = *(const float2*)&Ws2[k * 32 + tx * 2];
            float a0 = As[(ty * 4 + 0) * HD + k];
            float a1 = As[(ty * 4 + 1) * HD + k];
            float a2 = As[(ty * 4 + 2) * HD + k];
            float a3 = As[(ty * 4 + 3) * HD + k];
            acc2[0][0] += a0 * wv.x; acc2[0][1] += a0 * wv.y;
            acc2[1][0] += a1 * wv.x; acc2[1][1] += a1 * wv.y;
            acc2[2][0] += a2 * wv.x; acc2[2][1] += a2 * wv.y;
            acc2[3][0] += a3 * wv.x; acc2[3][1] += a3 * wv.y;
        }
        {
            int hb = ct * 32 + tx * 2;
            const float* XnT = g_X + 2 * XSZ + (size_t)t * TB;
#pragma unroll
            for (int i = 0; i < 4; i++) {
                int b = rt * 64 + ty * 4 + i;
                float2 xv = *(const float2*)&XnT[(size_t)b * HD + hb];
                float n0 = tanhf(acc2[i][0] + xv.x);
                float n1 = tanhf(acc2[i][1] + xv.y);
                float2 hv = __ldcg((const float2*)&g_h[(size_t)b * HD + hb]);
                float2 zv = __ldcg((const float2*)&g_z[(size_t)b * HD + hb]);
                float2 o;
                o.x = hv.x + zv.x * (n0 - hv.x);
                o.y = hv.y + zv.y * (n1 - hv.y);
                __stcg((float2*)&g_h[(size_t)b * HD + hb], o);
            }
        }
        gridbar(tgt); tgt += NCTA;
    }

    // write final h to output
    {
        const float4* hp = (const float4*)(g_h + (size_t)bid * 2048);
        float4* op = (float4*)out + (size_t)bid * 512;
        for (int i = tid; i < 512; i += 256) op[i] = __ldcg(hp + i);
    }
}

// ---------------- launcher -------------------------------------------------
extern "C" void kernel_launch(void* const* d_in, const int* in_sizes, int n_in,
                              void* d_out, int out_size) {
    const float* hs  = (const float*)d_in[0];
    const float* tgt = (const float*)d_in[1];
    const int*   len = (const int*)d_in[2];
    const float* W1  = (const float*)d_in[3];
    const float* b1  = (const float*)d_in[4];
    const float* W2  = (const float*)d_in[5];
    const float* Wr  = (const float*)d_in[6];
    const float* Wz  = (const float*)d_in[8];
    const float* Wn  = (const float*)d_in[10];
    float* out = (float*)d_out;
    (void)in_sizes; (void)n_in; (void)out_size;
    (void)d_in[7]; (void)d_in[9]; (void)d_in[11];
    const float* br = (const float*)d_in[7];
    const float* bz = (const float*)d_in[9];
    const float* bn = (const float*)d_in[11];

    k_reset<<<1, 1>>>();
    k_tproj<<<B, 128>>>(tgt, W1, b1);
    k_scores<<<B * 25, 128>>>(hs, W1, W2);
    k_softmax<<<B, 256>>>(len);
    k_xproj<<<dim3(12, 3200), 256>>>(hs, Wr, br, Wz, bz, Wn, bn);
    cudaFuncSetAttribute(k_recur, cudaFuncAttributeMaxDynamicSharedMemorySize, 163840);
    k_recur<<<NCTA, 256, 163840>>>(Wr, Wz, Wn, out);
}

// round 3
// speedup vs baseline: 1.4363x; 1.4363x over previous
#include <cuda_runtime.h>
#include <cuda_bf16.h>
#include <math.h>
#include <stdint.h>

#define B  1024
#define S  200
#define HD 256
#define AD 128

// ---------------- scratch (static device globals; no allocations) ----------
__device__ float g_tproj[B * AD];
__device__ float g_scores[B * S];
__device__ float g_att[S * B];                         // att transposed [t][b]
__device__ __align__(16) float g_X[3ull * S * B * HD]; // [gate][t][b][h]
__device__ __align__(16) float g_h[B * HD];
__device__ __align__(16) float g_rh[B * HD];
__device__ __align__(16) float g_z[B * HD];
__device__ unsigned int g_barcnt;

// bf16 split operands for tensor-core GEMMs
__device__ __align__(16) __nv_bfloat16 g_hsh[(size_t)B * S * HD];
__device__ __align__(16) __nv_bfloat16 g_hsl[(size_t)B * S * HD];
__device__ __align__(16) __nv_bfloat16 g_Wxh[768 * 256];   // [Wr;Wz;Wn] x-part
__device__ __align__(16) __nv_bfloat16 g_Wxl[768 * 256];
__device__ __align__(16) __nv_bfloat16 g_Wsh[128 * 256];   // W1 hidden part
__device__ __align__(16) __nv_bfloat16 g_Wsl[128 * 256];

static const size_t TB  = (size_t)B * HD;            // 262144
static const size_t XSZ = (size_t)S * B * HD;        // 52,428,800

__device__ __forceinline__ float sigf(float x) { return 1.0f / (1.0f + expf(-x)); }

__device__ __forceinline__ uint32_t smem_u32(const void* p) {
    uint32_t a;
    asm("{ .reg .u64 t; cvta.to.shared.u64 t, %1; cvt.u32.u64 %0, t; }"
        : "=r"(a) : "l"(p));
    return a;
}

__device__ __forceinline__ void ldmat4(uint32_t a[4], uint32_t addr) {
    asm volatile("ldmatrix.sync.aligned.m8n8.x4.shared.b16 {%0,%1,%2,%3}, [%4];"
                 : "=r"(a[0]), "=r"(a[1]), "=r"(a[2]), "=r"(a[3]) : "r"(addr));
}

#define MMA16816(d, a, bb) \
    asm volatile("mma.sync.aligned.m16n8k16.row.col.f32.bf16.bf16.f32 " \
        "{%0,%1,%2,%3}, {%4,%5,%6,%7}, {%8,%9}, {%0,%1,%2,%3};" \
        : "+f"((d)[0]), "+f"((d)[1]), "+f"((d)[2]), "+f"((d)[3]) \
        : "r"((a)[0]), "r"((a)[1]), "r"((a)[2]), "r"((a)[3]), \
          "r"((bb)[0]), "r"((bb)[1]))

// ---------------- reset barrier counter ------------------------------------
__global__ void k_reset() { g_barcnt = 0u; }

// ---------------- split fp32 -> bf16 hi/lo ----------------------------------
__global__ void k_cvt_hs(const float* __restrict__ hs) {
    size_t i = (size_t)blockIdx.x * 256 + threadIdx.x;   // float4 index
    float4 v = ((const float4*)hs)[i];
    union { __nv_bfloat16 b[4]; uint2 u; } H, L;
    H.b[0] = __float2bfloat16(v.x); L.b[0] = __float2bfloat16(v.x - __bfloat162float(H.b[0]));
    H.b[1] = __float2bfloat16(v.y); L.b[1] = __float2bfloat16(v.y - __bfloat162float(H.b[1]));
    H.b[2] = __float2bfloat16(v.z); L.b[2] = __float2bfloat16(v.z - __bfloat162float(H.b[2]));
    H.b[3] = __float2bfloat16(v.w); L.b[3] = __float2bfloat16(v.w - __bfloat162float(H.b[3]));
    ((uint2*)g_hsh)[i] = H.u;
    ((uint2*)g_hsl)[i] = L.u;
}

__global__ void k_cvt_w(const float* __restrict__ Wr, const float* __restrict__ Wz,
                        const float* __restrict__ Wn, const float* __restrict__ W1) {
    int row = blockIdx.x, k = threadIdx.x;
    float v; __nv_bfloat16 *dh, *dl; int idx;
    if (row < 768) {
        int g = row >> 8, c = row & 255;
        const float* W = (g == 0) ? Wr : (g == 1) ? Wz : Wn;
        v = W[c * 512 + k]; dh = g_Wxh; dl = g_Wxl; idx = row * 256 + k;
    } else {
        int a = row - 768;
        v = W1[a * 512 + k]; dh = g_Wsh; dl = g_Wsl; idx = a * 256 + k;
    }
    __nv_bfloat16 h = __float2bfloat16(v);
    dh[idx] = h;
    dl[idx] = __float2bfloat16(v - __bfloat162float(h));
}

// ---------------- tproj[b,a] = b1[a] + sum_d tgt[b,d]*W1[a,256+d] ----------
__global__ void k_tproj(const float* __restrict__ tgt,
                        const float* __restrict__ W1,
                        const float* __restrict__ b1) {
    __shared__ float ts[HD];
    int b = blockIdx.x, a = threadIdx.x;
    for (int i = threadIdx.x; i < HD; i += 128) ts[i] = tgt[(size_t)b * HD + i];
    __syncthreads();
    float s = b1[a];
    const float* w = W1 + (size_t)a * 512 + 256;
#pragma unroll 8
    for (int k = 0; k < HD; k++) s += ts[k] * w[k];
    g_tproj[b * AD + a] = s;
}

// =========== mma.sync bf16-split GEMM mainloop (128x128, Klog=768) =========
// smA/smB: [2 bufs][128 rows][40 bf16] (stride 40 = 80B, conflict-free)
// accumulators c[2 mfrag][8 nfrag][4] per thread; warp = 32(m) x 64(n)
__device__ __forceinline__ void gemm_ml(
    const __nv_bfloat16* __restrict__ Ah, const __nv_bfloat16* __restrict__ Al,
    const __nv_bfloat16* __restrict__ Bh, const __nv_bfloat16* __restrict__ Bl,
    __nv_bfloat16* smA, __nv_bfloat16* smB, float c[2][8][4])
{
    int tid = threadIdx.x, lane = tid & 31, wid = tid >> 5;
    int m0 = (wid & 3) * 32, n0 = (wid >> 2) * 64;
    uint32_t smA_u = smem_u32(smA);
    int r0 = tid >> 2, q = tid & 3;          // rows r0 and r0+64, 16B unit q

    uint4 ra0, ra1, rb0, rb1;
    // load chunk 0 (Ah x Bh, k0 = 0)
    ra0 = *(const uint4*)(Ah + r0 * 256 + q * 8);
    ra1 = *(const uint4*)(Ah + (r0 + 64) * 256 + q * 8);
    rb0 = *(const uint4*)(Bh + r0 * 256 + q * 8);
    rb1 = *(const uint4*)(Bh + (r0 + 64) * 256 + q * 8);
    *(uint4*)(smA + r0 * 40 + q * 8)        = ra0;
    *(uint4*)(smA + (r0 + 64) * 40 + q * 8) = ra1;
    *(uint4*)(smB + r0 * 40 + q * 8)        = rb0;
    *(uint4*)(smB + (r0 + 64) * 40 + q * 8) = rb1;
    __syncthreads();

    for (int kc = 0; kc < 24; kc++) {
        if (kc < 23) {
            int kn = kc + 1;
            const __nv_bfloat16* As = (kn < 16) ? Ah : Al;
            const __nv_bfloat16* Bs = (kn < 8) ? Bh : (kn < 16 ? Bl : Bh);
            int k0 = (kn & 7) * 32;
            ra0 = *(const uint4*)(As + r0 * 256 + k0 + q * 8);
            ra1 = *(const uint4*)(As + (r0 + 64) * 256 + k0 + q * 8);
            rb0 = *(const uint4*)(Bs + r0 * 256 + k0 + q * 8);
            rb1 = *(const uint4*)(Bs + (r0 + 64) * 256 + k0 + q * 8);
        }
        const __nv_bfloat16* bufB = smB + (kc & 1) * 5120;
        uint32_t abase = smA_u + (kc & 1) * 10240
                       + (uint32_t)(m0 + (lane & 15)) * 80 + ((lane >> 4) * 8) * 2;
#pragma unroll
        for (int ks = 0; ks < 2; ks++) {
            uint32_t af0[4], af1[4];
            ldmat4(af0, abase + ks * 32);
            ldmat4(af1, abase + 16 * 80 + ks * 32);
            uint32_t bfr[8][2];
#pragma unroll
            for (int nf = 0; nf < 8; nf++) {
                const uint32_t* bp = (const uint32_t*)
                    (bufB + (n0 + nf * 8 + (lane >> 2)) * 40 + ks * 16 + (lane & 3) * 2);
                bfr[nf][0] = bp[0];
                bfr[nf][1] = bp[4];
            }
#pragma unroll
            for (int nf = 0; nf < 8; nf++) {
                MMA16816(c[0][nf], af0, bfr[nf]);
                MMA16816(c[1][nf], af1, bfr[nf]);
            }
        }
        if (kc < 23) {
            int nb = (kc + 1) & 1;
            *(uint4*)(smA + nb * 5120 + r0 * 40 + q * 8)        = ra0;
            *(uint4*)(smA + nb * 5120 + (r0 + 64) * 40 + q * 8) = ra1;
            *(uint4*)(smB + nb * 5120 + r0 * 40 + q * 8)        = rb0;
            *(uint4*)(smB + nb * 5120 + (r0 + 64) * 40 + q * 8) = rb1;
            __syncthreads();
        }
    }
}

// ---------------- X projection via mma.sync --------------------------------
__global__ void __launch_bounds__(256) k_xproj_mma(
    const float* __restrict__ br, const float* __restrict__ bz,
    const float* __restrict__ bn) {
    extern __shared__ __align__(16) char dsm[];
    __nv_bfloat16* smA = (__nv_bfloat16*)dsm;
    __nv_bfloat16* smB = smA + 2 * 5120;
    int ntile = blockIdx.x % 6, mtile = blockIdx.x / 6;

    float c[2][8][4];
#pragma unroll
    for (int i = 0; i < 2; i++)
#pragma unroll
        for (int j = 0; j < 8; j++)
#pragma unroll
            for (int e = 0; e < 4; e++) c[i][j][e] = 0.0f;

    gemm_ml(g_hsh + (size_t)mtile * 128 * 256, g_hsl + (size_t)mtile * 128 * 256,
            g_Wxh + (size_t)ntile * 128 * 256, g_Wxl + (size_t)ntile * 128 * 256,
            smA, smB, c);

    int lane = threadIdx.x & 31, wid = threadIdx.x >> 5;
    int m0 = (wid & 3) * 32, n0 = (wid >> 2) * 64;
    int g = ntile >> 1, h0 = (ntile & 1) * 128;
    const float* bias = (g == 0) ? br : (g == 1) ? bz : bn;
    float2 bv[8];
#pragma unroll
    for (int nf = 0; nf < 8; nf++)
        bv[nf] = *(const float2*)(bias + h0 + n0 + nf * 8 + (lane & 3) * 2);

#pragma unroll
    for (int mf = 0; mf < 2; mf++)
#pragma unroll
        for (int p = 0; p < 2; p++) {
            int rg = mtile * 128 + m0 + mf * 16 + (lane >> 2) + p * 8;
            int b = rg / 200, s = rg - b * 200;
            float* dst = g_X + (size_t)g * XSZ + ((size_t)s * B + b) * 256 + h0;
#pragma unroll
            for (int nf = 0; nf < 8; nf++) {
                float2 o;
                o.x = c[mf][nf][2 * p + 0] + bv[nf].x;
                o.y = c[mf][nf][2 * p + 1] + bv[nf].y;
                *(float2*)(dst + n0 + nf * 8 + (lane & 3) * 2) = o;
            }
        }
}

// ---------------- attention scores via mma.sync ----------------------------
__global__ void __launch_bounds__(256) k_scores_mma(const float* __restrict__ W2) {
    extern __shared__ __align__(16) char dsm[];
    __nv_bfloat16* smA = (__nv_bfloat16*)dsm;
    __nv_bfloat16* smB = smA + 2 * 5120;
    float* Sres = (float*)(dsm + 40960);          // [128][132]
    float* red  = (float*)(dsm + 40960 + 67584);  // [128][2]
    int mtile = blockIdx.x;

    float c[2][8][4];
#pragma unroll
    for (int i = 0; i < 2; i++)
#pragma unroll
        for (int j = 0; j < 8; j++)
#pragma unroll
            for (int e = 0; e < 4; e++) c[i][j][e] = 0.0f;

    gemm_ml(g_hsh + (size_t)mtile * 128 * 256, g_hsl + (size_t)mtile * 128 * 256,
            g_Wsh, g_Wsl, smA, smB, c);

    int tid = threadIdx.x, lane = tid & 31, wid = tid >> 5;
    int m0 = (wid & 3) * 32, n0 = (wid >> 2) * 64;
#pragma unroll
    for (int mf = 0; mf < 2; mf++)
#pragma unroll
        for (int nf = 0; nf < 8; nf++) {
            int r0 = m0 + mf * 16 + (lane >> 2);
            int cc = n0 + nf * 8 + (lane & 3) * 2;
            Sres[r0 * 132 + cc]           = c[mf][nf][0];
            Sres[r0 * 132 + cc + 1]       = c[mf][nf][1];
            Sres[(r0 + 8) * 132 + cc]     = c[mf][nf][2];
            Sres[(r0 + 8) * 132 + cc + 1] = c[mf][nf][3];
        }
    __syncthreads();

    {
        int row = tid >> 1, half = tid & 1;
        int rg = mtile * 128 + row;
        int b = rg / 200;
        const float* tp = g_tproj + b * AD + half * 64;
        const float* w2 = W2 + half * 64;
        float part = 0.0f;
#pragma unroll 8
        for (int j = 0; j < 64; j++)
            part += fmaxf(Sres[row * 132 + half * 64 + j] + tp[j], 0.0f) * w2[j];
        red[row * 2 + half] = part;
    }
    __syncthreads();
    if (tid < 128)
        g_scores[mtile * 128 + tid] = red[tid * 2] + red[tid * 2 + 1];
}

// ---------------- masked softmax over S, output transposed [t][b] ----------
__global__ void k_softmax(const int* __restrict__ lengths) {
    __shared__ float red[256];
    int b = blockIdx.x, s = threadIdx.x;
    int len = lengths[b];
    float sc = -3.0e38f;
    if (s < S) sc = (s < len) ? g_scores[b * S + s] : -1e9f;
    red[s] = sc; __syncthreads();
    for (int o = 128; o; o >>= 1) {
        if (s < o) red[s] = fmaxf(red[s], red[s + o]);
        __syncthreads();
    }
    float mx = red[0]; __syncthreads();
    float e = (s < S) ? expf(sc - mx) : 0.0f;
    red[s] = e; __syncthreads();
    for (int o = 128; o; o >>= 1) {
        if (s < o) red[s] += red[s + o];
        __syncthreads();
    }
    float inv = 1.0f / red[0];
    if (s < S) g_att[s * B + b] = e * inv;
}

// ---------------- persistent AUGRU scan -----------------------------------
#define NCTA 128

__device__ __forceinline__ void gridbar(unsigned int target) {
    __threadfence();
    __syncthreads();
    if (threadIdx.x == 0) {
        atomicAdd(&g_barcnt, 1u);
        while (*(volatile unsigned int*)&g_barcnt < target) { }
        __threadfence();
    }
    __syncthreads();
}

__global__ void __launch_bounds__(256, 1) k_recur(
    const float* __restrict__ Wr, const float* __restrict__ Wz,
    const float* __restrict__ Wn, float* __restrict__ out) {
    extern __shared__ float smem[];
    float* Ws1 = smem;                       // [256][64]  phase1 weight (k-major)
    float* Ws2 = smem + 256 * 64;            // [256][32]  phase2 weight (k-major)
    float* As  = smem + 256 * 64 + 256 * 32; // [64][256]  input tile

    int tid = threadIdx.x;
    int bid = blockIdx.x;        // 0..127
    int rt  = bid >> 3;          // row tile 0..15 (64 batch rows each)
    int ct  = bid & 7;           // col tile

    {
        const float* Wg1 = (ct < 4) ? Wr : Wz;
        int hbase = (ct < 4) ? ct * 64 : (ct - 4) * 64;
        for (int i = tid; i < 64 * 64; i += 256) {
            int c = i >> 6, kv = i & 63;
            float4 w = *(const float4*)&Wg1[(size_t)(hbase + c) * 512 + 256 + kv * 4];
            Ws1[(kv * 4 + 0) * 64 + c] = w.x;
            Ws1[(kv * 4 + 1) * 64 + c] = w.y;
            Ws1[(kv * 4 + 2) * 64 + c] = w.z;
            Ws1[(kv * 4 + 3) * 64 + c] = w.w;
        }
        for (int i = tid; i < 32 * 64; i += 256) {
            int c = i >> 6, kv = i & 63;
            float4 w = *(const float4*)&Wn[(size_t)(ct * 32 + c) * 512 + 256 + kv * 4];
            Ws2[(kv * 4 + 0) * 32 + c] = w.x;
            Ws2[(kv * 4 + 1) * 32 + c] = w.y;
            Ws2[(kv * 4 + 2) * 32 + c] = w.z;
            Ws2[(kv * 4 + 3) * 32 + c] = w.w;
        }
    }
    {
        float4 zf = make_float4(0.f, 0.f, 0.f, 0.f);
        float4* hp = (float4*)(g_h + (size_t)bid * 2048);
        for (int i = tid; i < 512; i += 256) hp[i] = zf;
    }
    unsigned int tgt = NCTA;
    gridbar(tgt); tgt += NCTA;

    int tx = tid & 15, ty = tid >> 4;

    for (int t = 0; t < S; t++) {
        {
            const float4* src = (const float4*)(g_h + (size_t)rt * 64 * HD);
            float4* dst = (float4*)As;
            for (int i = tid; i < 4096; i += 256) dst[i] = __ldcg(src + i);
        }
        __syncthreads();
        float acc[4][4];
#pragma unroll
        for (int i = 0; i < 4; i++)
#pragma unroll
            for (int j = 0; j < 4; j++) acc[i][j] = 0.0f;
#pragma unroll 4
        for (int k = 0; k < HD; k++) {
            float4 wv = *(const float4*)&Ws1[k * 64 + tx * 4];
            float a0 = As[(ty * 4 + 0) * HD + k];
            float a1 = As[(ty * 4 + 1) * HD + k];
            float a2 = As[(ty * 4 + 2) * HD + k];
            float a3 = As[(ty * 4 + 3) * HD + k];
            acc[0][0] += a0 * wv.x; acc[0][1] += a0 * wv.y; acc[0][2] += a0 * wv.z; acc[0][3] += a0 * wv.w;
            acc[1][0] += a1 * wv.x; acc[1][1] += a1 * wv.y; acc[1][2] += a1 * wv.z; acc[1][3] += a1 * wv.w;
            acc[2][0] += a2 * wv.x; acc[2][1] += a2 * wv.y; acc[2][2] += a2 * wv.z; acc[2][3] += a2 * wv.w;
            acc[3][0] += a3 * wv.x; acc[3][1] += a3 * wv.y; acc[3][2] += a3 * wv.z; acc[3][3] += a3 * wv.w;
        }
        if (ct < 4) {
            int hb = ct * 64 + tx * 4;
            const float* XrT = g_X + (size_t)t * TB;
#pragma unroll
            for (int i = 0; i < 4; i++) {
                int b = rt * 64 + ty * 4 + i;
                float4 xv = *(const float4*)&XrT[(size_t)b * HD + hb];
                float4 hv = *(const float4*)&As[(ty * 4 + i) * HD + hb];
                float4 o;
                o.x = sigf(acc[i][0] + xv.x) * hv.x;
                o.y = sigf(acc[i][1] + xv.y) * hv.y;
                o.z = sigf(acc[i][2] + xv.z) * hv.z;
                o.w = sigf(acc[i][3] + xv.w) * hv.w;
                __stcg((float4*)&g_rh[(size_t)b * HD + hb], o);
            }
        } else {
            int hb = (ct - 4) * 64 + tx * 4;
            const float* XzT = g_X + XSZ + (size_t)t * TB;
#pragma unroll
            for (int i = 0; i < 4; i++) {
                int b = rt * 64 + ty * 4 + i;
                float av = g_att[t * B + b];
                float4 xv = *(const float4*)&XzT[(size_t)b * HD + hb];
                float4 o;
                o.x = sigf(acc[i][0] + xv.x) * av;
                o.y = sigf(acc[i][1] + xv.y) * av;
                o.z = sigf(acc[i][2] + xv.z) * av;
                o.w = sigf(acc[i][3] + xv.w) * av;
                __stcg((float4*)&g_z[(size_t)b * HD + hb], o);
            }
        }
        gridbar(tgt); tgt += NCTA;

        {
            const float4* src = (const float4*)(g_rh + (size_t)rt * 64 * HD);
            float4* dst = (float4*)As;
            for (int i = tid; i < 4096; i += 256) dst[i] = __ldcg(src + i);
        }
        __syncthreads();
        float acc2[4][2];
#pragma unroll
        for (int i = 0; i < 4; i++) { acc2[i][0] = 0.0f; acc2[i][1] = 0.0f; }
#pragma unroll 4
        for (int k = 0; k < HD; k++) {
            float2 wv = *(const float2*)&Ws2[k * 32 + tx * 2];
            float a0 = As[(ty * 4 + 0) * HD + k];
            float a1 = As[(ty * 4 + 1) * HD + k];
            float a2 = As[(ty * 4 + 2) * HD + k];
            float a3 = As[(ty * 4 + 3) * HD + k];
            acc2[0][0] += a0 * wv.x; acc2[0][1] += a0 * wv.y;
            acc2[1][0] += a1 * wv.x; acc2[1][1] += a1 * wv.y;
            acc2[2][0] += a2 * wv.x; acc2[2][1] += a2 * wv.y;
            acc2[3][0] += a3 * wv.x; acc2[3][1] += a3 * wv.y;
        }
        {
            int hb = ct * 32 + tx * 2;
            const float* XnT = g_X + 2 * XSZ + (size_t)t * TB;
#pragma unroll
            for (int i = 0; i < 4; i++) {
                int b = rt * 64 + ty * 4 + i;
                float2 xv = *(const float2*)&XnT[(size_t)b * HD + hb];
                float n0 = tanhf(acc2[i][0] + xv.x);
                float n1 = tanhf(acc2[i][1] + xv.y);
                float2 hv = __ldcg((const float2*)&g_h[(size_t)b * HD + hb]);
                float2 zv = __ldcg((const float2*)&g_z[(size_t)b * HD + hb]);
                float2 o;
                o.x = hv.x + zv.x * (n0 - hv.x);
                o.y = hv.y + zv.y * (n1 - hv.y);
                __stcg((float2*)&g_h[(size_t)b * HD + hb], o);
            }
        }
        gridbar(tgt); tgt += NCTA;
    }

    {
        const float4* hp = (const float4*)(g_h + (size_t)bid * 2048);
        float4* op = (float4*)out + (size_t)bid * 512;
        for (int i = tid; i < 512; i += 256) op[i] = __ldcg(hp + i);
    }
}

// ---------------- launcher -------------------------------------------------
extern "C" void kernel_launch(void* const* d_in, const int* in_sizes, int n_in,
                              void* d_out, int out_size) {
    const float* hs  = (const float*)d_in[0];
    const float* tgt = (const float*)d_in[1];
    const int*   len = (const int*)d_in[2];
    const float* W1  = (const float*)d_in[3];
    const float* b1  = (const float*)d_in[4];
    const float* W2  = (const float*)d_in[5];
    const float* Wr  = (const float*)d_in[6];
    const float* br  = (const float*)d_in[7];
    const float* Wz  = (const float*)d_in[8];
    const float* bz  = (const float*)d_in[9];
    const float* Wn  = (const float*)d_in[10];
    const float* bn  = (const float*)d_in[11];
    float* out = (float*)d_out;
    (void)in_sizes; (void)n_in; (void)out_size;

    cudaFuncSetAttribute(k_recur, cudaFuncAttributeMaxDynamicSharedMemorySize, 163840);
    cudaFuncSetAttribute(k_scores_mma, cudaFuncAttributeMaxDynamicSharedMemorySize, 110592);
    cudaFuncSetAttribute(k_xproj_mma, cudaFuncAttributeMaxDynamicSharedMemorySize, 40960);

    k_reset<<<1, 1>>>();
    k_cvt_hs<<<51200, 256>>>(hs);               // 52.4M elems, float4/thread
    k_cvt_w<<<896, 256>>>(Wr, Wz, Wn, W1);
    k_tproj<<<B, 128>>>(tgt, W1, b1);
    k_scores_mma<<<1600, 256, 110592>>>(W2);
    k_softmax<<<B, 256>>>(len);
    k_xproj_mma<<<9600, 256, 40960>>>(br, bz, bn);
    k_recur<<<NCTA, 256, 163840>>>(Wr, Wz, Wn, out);
}